// round 16
// baseline (speedup 1.0000x reference)
#include <cuda_runtime.h>
#include <cuda_bf16.h>
#include <cuda_fp16.h>
#include <cstdint>
#include <math.h>

// Problem constants
#define B_  2
#define N_  2048
#define C_  1024
#define H_  16
#define D_  64
#define M_  (B_ * N_)        // 4096
#define K3_ (3 * C_)         // 3072

// ---------------------------------------------------------------------------
// Scratch (device globals)
// ---------------------------------------------------------------------------
__device__ __half g_xh[M_ * C_];                       // x single fp16
__device__ __half g_w1h[K3_ * C_];                     // qkv_w single fp16
__device__ __half g_w2h[C_ * C_];                      // proj_w single fp16
__device__ __half g_a[M_ * C_];                        // attention out single fp16
// head-major [b*16+h][n][64]
__device__ __half g_q[B_*H_*N_*D_];                    // Q single (pre-scaled)
__device__ __half g_k[B_*H_*N_*D_];                    // K single
__device__ __half g_v[B_*H_*N_*D_];                    // V single
__device__ float g_cos[1024 * 32], g_sin[1024 * 32];

// ---------------------------------------------------------------------------
// Helpers
// ---------------------------------------------------------------------------
__device__ __forceinline__ uint32_t smem_u32(const void* p) {
    uint32_t a;
    asm("{ .reg .u64 t; cvta.to.shared.u64 t, %1; cvt.u32.u64 %0, t; }" : "=r"(a) : "l"(p));
    return a;
}
__device__ __forceinline__ void ldsm4(uint32_t* r, uint32_t addr) {
    asm volatile("ldmatrix.sync.aligned.m8n8.x4.shared.b16 {%0,%1,%2,%3}, [%4];"
                 : "=r"(r[0]), "=r"(r[1]), "=r"(r[2]), "=r"(r[3]) : "r"(addr));
}
__device__ __forceinline__ void ldsm4t(uint32_t* r, uint32_t addr) {
    asm volatile("ldmatrix.sync.aligned.m8n8.x4.trans.shared.b16 {%0,%1,%2,%3}, [%4];"
                 : "=r"(r[0]), "=r"(r[1]), "=r"(r[2]), "=r"(r[3]) : "r"(addr));
}
// fp32-accumulator HMMA
__device__ __forceinline__ void mma16816(float* c, const uint32_t* a, uint32_t b0, uint32_t b1) {
    asm volatile("mma.sync.aligned.m16n8k16.row.col.f32.f16.f16.f32 "
                 "{%0,%1,%2,%3}, {%4,%5,%6,%7}, {%8,%9}, {%0,%1,%2,%3};"
                 : "+f"(c[0]), "+f"(c[1]), "+f"(c[2]), "+f"(c[3])
                 : "r"(a[0]), "r"(a[1]), "r"(a[2]), "r"(a[3]), "r"(b0), "r"(b1));
}
// fp16-accumulator HMMA
__device__ __forceinline__ void mma16816h(uint32_t* d, const uint32_t* a, uint32_t b0, uint32_t b1) {
    asm volatile("mma.sync.aligned.m16n8k16.row.col.f16.f16.f16.f16 "
                 "{%0,%1}, {%2,%3,%4,%5}, {%6,%7}, {%0,%1};"
                 : "+r"(d[0]), "+r"(d[1])
                 : "r"(a[0]), "r"(a[1]), "r"(a[2]), "r"(a[3]), "r"(b0), "r"(b1));
}
__device__ __forceinline__ uint32_t packh(float a, float b) {
    uint32_t r;
    asm("cvt.rn.f16x2.f32 %0, %1, %2;" : "=r"(r) : "f"(b), "f"(a));
    return r;
}
__device__ __forceinline__ float fexp2(float x) {
    float r;
    asm("ex2.approx.f32 %0, %1;" : "=f"(r) : "f"(x));
    return r;
}
__device__ __forceinline__ uint32_t h2exp2(uint32_t x) {
    uint32_t r;
    asm("ex2.approx.f16x2 %0, %1;" : "=r"(r) : "r"(x));
    return r;
}
__device__ __forceinline__ uint32_t h2max(uint32_t a, uint32_t b) {
    uint32_t r;
    asm("max.f16x2 %0, %1, %2;" : "=r"(r) : "r"(a), "r"(b));
    return r;
}
__device__ __forceinline__ uint32_t h2sub(uint32_t a, uint32_t b) {
    uint32_t r;
    asm("sub.f16x2 %0, %1, %2;" : "=r"(r) : "r"(a), "r"(b));
    return r;
}

#define QSCALE 0.1803368801111137f   // 0.125 * log2(e)
#define ONES_H2 0x3C003C00u          // fp16x2 {1.0, 1.0}

// ---------------------------------------------------------------------------
// Merged fp32 -> fp16 convert
// ---------------------------------------------------------------------------
#define NX4  (M_ * C_ / 4)
#define NW14 (K3_ * C_ / 4)
#define NW24 (C_ * C_ / 4)

__global__ __launch_bounds__(256) void cvt_all(const float4* __restrict__ x,
                                               const float4* __restrict__ w1,
                                               const float4* __restrict__ w2,
                                               uint2* __restrict__ xh,
                                               uint2* __restrict__ w1h,
                                               uint2* __restrict__ w2h)
{
    int i = blockIdx.x * 256 + threadIdx.x;
    const float4* s;
    uint2* d;
    if (i < NX4)              { s = x + i;                 d = xh + i; }
    else if (i < NX4 + NW14)  { s = w1 + (i - NX4);        d = w1h + (i - NX4); }
    else                      { s = w2 + (i - NX4 - NW14); d = w2h + (i - NX4 - NW14); }
    float4 v = *s;
    *d = make_uint2(packh(v.x, v.y), packh(v.z, v.w));
}

// ---------------------------------------------------------------------------
// RoPE tables
// ---------------------------------------------------------------------------
__global__ __launch_bounds__(256) void rope_table()
{
    int idx = blockIdx.x * 256 + threadIdx.x;          // 32768
    int pos = idx >> 5, lane = idx & 31;
    float e = (float)(2 * lane) * (1.0f / 64.0f);
    float inv = expf(-9.210340371976184f * e);
    float ang = (float)pos * inv;
    g_cos[idx] = cosf(ang);
    g_sin[idx] = sinf(ang);
}

// ---------------------------------------------------------------------------
// Shared GEMM config (block 128x128, K=1024, chunk 32, 8 warps 4x2)
// ---------------------------------------------------------------------------
#define STAGE_B 20480
#define GEMM_SMEM (3 * STAGE_B)   // 61440

// ---------------------------------------------------------------------------
// QKV GEMM (single-pass fp16) with FUSED RMSNorm + RoPE + fp16 emit.
// ---------------------------------------------------------------------------
__global__ __launch_bounds__(256, 2) void gemm_qkv_fused(
    const __half* __restrict__ Ah, const __half* __restrict__ Bh,
    const float* __restrict__ bias,
    const float* __restrict__ qn_w, const float* __restrict__ kn_w)
{
    extern __shared__ char sm[];
    const uint32_t sbase = smem_u32(sm);
    const int tid = threadIdx.x;
    const int lane = tid & 31;
    const int wid = tid >> 5;
    const int warp_m = wid >> 1;
    const int warp_n = wid & 1;
    const int row0 = blockIdx.y * 128;
    const int col0 = blockIdx.x * 128;

    float acc[2][8][4];
#pragma unroll
    for (int a = 0; a < 2; a++)
#pragma unroll
        for (int b = 0; b < 8; b++)
#pragma unroll
            for (int c = 0; c < 4; c++) acc[a][b][c] = 0.0f;

    const __half* srcs[2] = { Ah + (size_t)row0 * 1024, Bh + (size_t)col0 * 1024 };

    auto load_stage = [&](int c, int buf) {
#pragma unroll
        for (int i = 0; i < 4; i++) {
            int lin = tid + i * 256;
            int mat = lin >> 9;
            int rem = lin & 511;
            int row = rem >> 2;
            int ch = rem & 3;
            const __half* s = srcs[mat] + (size_t)row * 1024 + c * 32 + ch * 8;
            uint32_t d = sbase + buf * STAGE_B + mat * 10240 + (uint32_t)(row * 40 + ch * 8) * 2;
            asm volatile("cp.async.cg.shared.global [%0], [%1], 16;" :: "r"(d), "l"(s));
        }
        asm volatile("cp.async.commit_group;");
    };

    load_stage(0, 0);
    load_stage(1, 1);
    for (int c = 0; c < 32; c++) {
        const int buf = c % 3;
        if (c + 2 < 32) { load_stage(c + 2, (c + 2) % 3); asm volatile("cp.async.wait_group 2;"); }
        else if (c + 1 < 32) { asm volatile("cp.async.wait_group 1;"); }
        else { asm volatile("cp.async.wait_group 0;"); }
        __syncthreads();
        const uint32_t base = sbase + buf * STAGE_B;
#pragma unroll
        for (int kk = 0; kk < 2; kk++) {
            uint32_t ah[2][4], bh[4][4];
            int arow = warp_m * 32 + (lane & 15);
            int acol = kk * 16 + (lane >> 4) * 8;
            uint32_t aoff = (uint32_t)(arow * 40 + acol) * 2;
            ldsm4(ah[0], base + aoff);
            ldsm4(ah[1], base + aoff + 1280);
            int g = lane >> 3, l7 = lane & 7;
#pragma unroll
            for (int p = 0; p < 4; p++) {
                int brow = warp_n * 64 + (p * 2 + (g >> 1)) * 8 + l7;
                int bcol = kk * 16 + (g & 1) * 8;
                ldsm4(bh[p], base + 10240 + (uint32_t)(brow * 40 + bcol) * 2);
            }
#pragma unroll
            for (int tm = 0; tm < 2; tm++)
#pragma unroll
                for (int tn = 0; tn < 8; tn++)
                    mma16816(acc[tm][tn], ah[tm],
                             bh[tn >> 1][(tn & 1) * 2], bh[tn >> 1][(tn & 1) * 2 + 1]);
        }
        __syncthreads();
    }

    // ---- fused epilogue ----
    const int sec = col0 >> 10;                         // 0=q, 1=k, 2=v
    const int head = ((col0 & 1023) >> 6) + warp_n;
    const int d0 = (lane & 3) * 2;

    float bs[8][2], wv[8][2];
    const float* w = (sec == 1) ? kn_w : qn_w;
#pragma unroll
    for (int tn = 0; tn < 8; tn++) {
        int d = tn * 8 + d0;
        int col = col0 + warp_n * 64 + d;
        bs[tn][0] = __ldg(&bias[col]);
        bs[tn][1] = __ldg(&bias[col + 1]);
        if (sec < 2) { wv[tn][0] = __ldg(&w[d]); wv[tn][1] = __ldg(&w[d + 1]); }
    }

    auto process_row = [&](float v[8][2], int m) {
        const int n = m & 2047;
        const int bb = m >> 11;
        const size_t obase = (((size_t)(bb * 16 + head)) * 2048 + n) * 64;
        if (sec == 2) {
#pragma unroll
            for (int tn = 0; tn < 8; tn++)
                *reinterpret_cast<uint32_t*>(&g_v[obase + tn * 8 + d0]) = packh(v[tn][0], v[tn][1]);
            return;
        }
        float ss = 0.0f;
#pragma unroll
        for (int tn = 0; tn < 8; tn++) ss += v[tn][0] * v[tn][0] + v[tn][1] * v[tn][1];
        ss += __shfl_xor_sync(0xffffffffu, ss, 1);
        ss += __shfl_xor_sync(0xffffffffu, ss, 2);
        float rs = rsqrtf(ss * (1.0f / 64.0f) + 1e-6f);
#pragma unroll
        for (int tn = 0; tn < 8; tn++) {
            v[tn][0] *= rs * wv[tn][0];
            v[tn][1] *= rs * wv[tn][1];
        }
        int pos = (n < 1024) ? n : ((n < 1536) ? (n - 1024) : -1);
        if (pos >= 0) {
#pragma unroll
            for (int tn = 0; tn < 4; tn++) {
                int idx = pos * 32 + tn * 8 + d0;
#pragma unroll
                for (int j = 0; j < 2; j++) {
                    float cs = g_cos[idx + j], sn = g_sin[idx + j];
                    float t1 = v[tn][j], t2 = v[tn + 4][j];
                    v[tn][j]     = t1 * cs - t2 * sn;
                    v[tn + 4][j] = t2 * cs + t1 * sn;
                }
            }
        }
        if (sec == 0) {
#pragma unroll
            for (int tn = 0; tn < 8; tn++)
                *reinterpret_cast<uint32_t*>(&g_q[obase + tn * 8 + d0]) =
                    packh(v[tn][0] * QSCALE, v[tn][1] * QSCALE);
        } else {
#pragma unroll
            for (int tn = 0; tn < 8; tn++)
                *reinterpret_cast<uint32_t*>(&g_k[obase + tn * 8 + d0]) = packh(v[tn][0], v[tn][1]);
        }
    };

#pragma unroll
    for (int tm = 0; tm < 2; tm++) {
        const int mA = row0 + warp_m * 32 + tm * 16 + (lane >> 2);
        float vA[8][2], vB[8][2];
#pragma unroll
        for (int tn = 0; tn < 8; tn++) {
            vA[tn][0] = acc[tm][tn][0] + bs[tn][0];
            vA[tn][1] = acc[tm][tn][1] + bs[tn][1];
            vB[tn][0] = acc[tm][tn][2] + bs[tn][0];
            vB[tn][1] = acc[tm][tn][3] + bs[tn][1];
        }
        process_row(vA, mA);
        process_row(vB, mA + 8);
    }
}

// ---------------------------------------------------------------------------
// Generic single-pass fp16 GEMM (proj): out = A.B^T + bias
// ---------------------------------------------------------------------------
__global__ __launch_bounds__(256, 2) void gemm_mma(
    const __half* __restrict__ Ah, const __half* __restrict__ Bh,
    const float* __restrict__ bias, float* __restrict__ out, int ostride)
{
    extern __shared__ char sm[];
    const uint32_t sbase = smem_u32(sm);
    const int tid = threadIdx.x;
    const int lane = tid & 31;
    const int wid = tid >> 5;
    const int warp_m = wid >> 1;
    const int warp_n = wid & 1;
    const int row0 = blockIdx.y * 128;
    const int col0 = blockIdx.x * 128;

    float acc[2][8][4];
#pragma unroll
    for (int a = 0; a < 2; a++)
#pragma unroll
        for (int b = 0; b < 8; b++)
#pragma unroll
            for (int c = 0; c < 4; c++) acc[a][b][c] = 0.0f;

    const __half* srcs[2] = { Ah + (size_t)row0 * 1024, Bh + (size_t)col0 * 1024 };

    auto load_stage = [&](int c, int buf) {
#pragma unroll
        for (int i = 0; i < 4; i++) {
            int lin = tid + i * 256;
            int mat = lin >> 9;
            int rem = lin & 511;
            int row = rem >> 2;
            int ch = rem & 3;
            const __half* s = srcs[mat] + (size_t)row * 1024 + c * 32 + ch * 8;
            uint32_t d = sbase + buf * STAGE_B + mat * 10240 + (uint32_t)(row * 40 + ch * 8) * 2;
            asm volatile("cp.async.cg.shared.global [%0], [%1], 16;" :: "r"(d), "l"(s));
        }
        asm volatile("cp.async.commit_group;");
    };

    load_stage(0, 0);
    load_stage(1, 1);
    for (int c = 0; c < 32; c++) {
        const int buf = c % 3;
        if (c + 2 < 32) { load_stage(c + 2, (c + 2) % 3); asm volatile("cp.async.wait_group 2;"); }
        else if (c + 1 < 32) { asm volatile("cp.async.wait_group 1;"); }
        else { asm volatile("cp.async.wait_group 0;"); }
        __syncthreads();
        const uint32_t base = sbase + buf * STAGE_B;
#pragma unroll
        for (int kk = 0; kk < 2; kk++) {
            uint32_t ah[2][4], bh[4][4];
            int arow = warp_m * 32 + (lane & 15);
            int acol = kk * 16 + (lane >> 4) * 8;
            uint32_t aoff = (uint32_t)(arow * 40 + acol) * 2;
            ldsm4(ah[0], base + aoff);
            ldsm4(ah[1], base + aoff + 1280);
            int g = lane >> 3, l7 = lane & 7;
#pragma unroll
            for (int p = 0; p < 4; p++) {
                int brow = warp_n * 64 + (p * 2 + (g >> 1)) * 8 + l7;
                int bcol = kk * 16 + (g & 1) * 8;
                ldsm4(bh[p], base + 10240 + (uint32_t)(brow * 40 + bcol) * 2);
            }
#pragma unroll
            for (int tm = 0; tm < 2; tm++)
#pragma unroll
                for (int tn = 0; tn < 8; tn++)
                    mma16816(acc[tm][tn], ah[tm],
                             bh[tn >> 1][(tn & 1) * 2], bh[tn >> 1][(tn & 1) * 2 + 1]);
        }
        __syncthreads();
    }

#pragma unroll
    for (int tm = 0; tm < 2; tm++) {
        int mb = row0 + warp_m * 32 + tm * 16 + (lane >> 2);
#pragma unroll
        for (int tn = 0; tn < 8; tn++) {
            int col = col0 + warp_n * 64 + tn * 8 + (lane & 3) * 2;
            float b0 = __ldg(&bias[col]), b1 = __ldg(&bias[col + 1]);
            *reinterpret_cast<float2*>(&out[(size_t)mb * ostride + col]) =
                make_float2(acc[tm][tn][0] + b0, acc[tm][tn][1] + b1);
            *reinterpret_cast<float2*>(&out[(size_t)(mb + 8) * ostride + col]) =
                make_float2(acc[tm][tn][2] + b0, acc[tm][tn][3] + b1);
        }
    }
}

// ---------------------------------------------------------------------------
// Flash attention: 128 q/CTA, warp = 16 rows, 2 CTAs/SM (4 warps/SMSP for
// latency hiding). fp16-acc QK^T, f16x2 softmax, MMA row-sums, 128-key tiles.
// ---------------------------------------------------------------------------
#define RS   144
#define KVB  36864                // per buffer: K 128x144 + V 128x144
#define OVV  18432                // V offset within buffer
#define ATTN_SMEM (2 * KVB)       // 73728 (x2 CTAs = 147KB/SM)

__global__ __launch_bounds__(256, 2) void attn_mma()
{
    extern __shared__ char sm[];
    const uint32_t sbase = smem_u32(sm);
    const int tid = threadIdx.x;
    const int lane = tid & 31;
    const int wid = tid >> 5;
    const int q0 = blockIdx.x * 128;
    const int h = blockIdx.y;
    const int b = blockIdx.z;
    const size_t hb = ((size_t)(b * 16 + h)) * 2048 * 64;

    const __half* q_g = g_q + hb + (size_t)q0 * 64;
    const __half* k_g = g_k + hb;
    const __half* v_g = g_v + hb;

    // ---- stage Q (128 rows) through buffer region, hoist ----
    {
#pragma unroll
        for (int i = 0; i < 4; i++) {
            int lin = tid + i * 256;          // 0..1023 (128 rows x 8 chunks)
            int row = lin >> 3;
            int ch = lin & 7;
            const __half* s = q_g + (size_t)row * 64 + ch * 8;
            uint32_t d = sbase + (uint32_t)(row * RS + ch * 16);
            asm volatile("cp.async.cg.shared.global [%0], [%1], 16;" :: "r"(d), "l"(s));
        }
        asm volatile("cp.async.commit_group;");
        asm volatile("cp.async.wait_group 0;");
        __syncthreads();
    }

    uint32_t aq[4][4];
    {
        const int arow = wid * 16 + (lane & 15);
        const int acolb = (lane >> 4) * 16;
#pragma unroll
        for (int kc = 0; kc < 4; kc++)
            ldsm4(aq[kc], sbase + (uint32_t)(arow * RS + kc * 32 + acolb));
    }
    __syncthreads();   // all warps hoisted before KV overwrites Q

    // loads a 128-key tile (K 128 rows + V 128 rows)
    auto load_kv = [&](int t, int buf) {
        const uint32_t dbase = sbase + buf * KVB;
#pragma unroll
        for (int i = 0; i < 8; i++) {
            int lin = tid + i * 256;          // 0..2047
            int mat = lin >> 10;              // 0=K, 1=V
            int rem = lin & 1023;
            int row = rem >> 3;
            int ch = rem & 7;
            const __half* s = (mat ? v_g : k_g) + (size_t)t * 128 * 64 + (size_t)row * 64 + ch * 8;
            uint32_t d = dbase + mat * OVV + (uint32_t)(row * RS + ch * 16);
            asm volatile("cp.async.cg.shared.global [%0], [%1], 16;" :: "r"(d), "l"(s));
        }
        asm volatile("cp.async.commit_group;");
    };

    load_kv(0, 0);
    load_kv(1, 1);
    asm volatile("cp.async.wait_group 1;");
    __syncthreads();

    float m0 = -30000.0f, m1 = -30000.0f, l0 = 0.0f, l1 = 0.0f;
    float o[8][4];
#pragma unroll
    for (int nd = 0; nd < 8; nd++)
#pragma unroll
        for (int j = 0; j < 4; j++) o[nd][j] = 0.0f;

    const int g = lane >> 3, l7 = lane & 7;

    for (int t = 0; t < 16; t++) {
        const uint32_t kbuf = sbase + (t & 1) * KVB;

#pragma unroll
        for (int sub = 0; sub < 2; sub++) {
            const uint32_t koff = kbuf + (uint32_t)(sub * 64 * RS);
            const uint32_t voff = kbuf + OVV + (uint32_t)(sub * 64 * RS);

            // ---- S = Q K^T in fp16 accumulators ----
            uint32_t d[8][2];
#pragma unroll
            for (int tn = 0; tn < 8; tn++) { d[tn][0] = 0u; d[tn][1] = 0u; }

#pragma unroll
            for (int kc = 0; kc < 4; kc++) {
                uint32_t bh[4][4];
#pragma unroll
                for (int p = 0; p < 4; p++) {
                    int brow = (p * 2 + (g >> 1)) * 8 + l7;
                    int bcolb = kc * 32 + (g & 1) * 16;
                    ldsm4(bh[p], koff + (uint32_t)(brow * RS + bcolb));
                }
#pragma unroll
                for (int tn = 0; tn < 8; tn++)
                    mma16816h(d[tn], aq[kc],
                              bh[tn >> 1][(tn & 1) * 2], bh[tn >> 1][(tn & 1) * 2 + 1]);
            }

            // ---- online softmax in f16x2 domain ----
            uint32_t m20 = d[0][0], m21 = d[0][1];
#pragma unroll
            for (int tn = 1; tn < 8; tn++) {
                m20 = h2max(m20, d[tn][0]);
                m21 = h2max(m21, d[tn][1]);
            }
            m20 = h2max(m20, __shfl_xor_sync(0xffffffffu, m20, 1));
            m20 = h2max(m20, __shfl_xor_sync(0xffffffffu, m20, 2));
            m21 = h2max(m21, __shfl_xor_sync(0xffffffffu, m21, 1));
            m21 = h2max(m21, __shfl_xor_sync(0xffffffffu, m21, 2));
            __half2 h0 = *reinterpret_cast<__half2*>(&m20);
            __half2 h1 = *reinterpret_cast<__half2*>(&m21);
            float mx0 = fmaxf(__low2float(h0), __high2float(h0));
            float mx1 = fmaxf(__low2float(h1), __high2float(h1));
            float mn0 = fmaxf(m0, mx0), mn1 = fmaxf(m1, mx1);
            float al0 = fexp2(m0 - mn0), al1 = fexp2(m1 - mn1);
            m0 = mn0; m1 = mn1;
            uint32_t mn2a = packh(mn0, mn0);
            uint32_t mn2b = packh(mn1, mn1);
#pragma unroll
            for (int nd = 0; nd < 8; nd++) {
                o[nd][0] *= al0; o[nd][1] *= al0;
                o[nd][2] *= al1; o[nd][3] *= al1;
            }

            // ---- per-kc: exp2 -> P frags, rowsum MMA, PV MMA ----
            float sac[4] = {0.0f, 0.0f, 0.0f, 0.0f};
#pragma unroll
            for (int kc = 0; kc < 4; kc++) {
                uint32_t p[4];
                p[0] = h2exp2(h2sub(d[2 * kc][0],     mn2a));
                p[1] = h2exp2(h2sub(d[2 * kc][1],     mn2b));
                p[2] = h2exp2(h2sub(d[2 * kc + 1][0], mn2a));
                p[3] = h2exp2(h2sub(d[2 * kc + 1][1], mn2b));
                mma16816(sac, p, ONES_H2, ONES_H2);
#pragma unroll
                for (int dp = 0; dp < 4; dp++) {
                    int vrow = kc * 16 + (g & 1) * 8 + l7;
                    int vcolb = dp * 32 + (g >> 1) * 16;
                    uint32_t vh[4];
                    ldsm4t(vh, voff + (uint32_t)(vrow * RS + vcolb));
                    mma16816(o[dp * 2],     p, vh[0], vh[1]);
                    mma16816(o[dp * 2 + 1], p, vh[2], vh[3]);
                }
            }
            l0 = l0 * al0 + sac[0];
            l1 = l1 * al1 + sac[2];
        }

        __syncthreads();
        if (t + 2 < 16) load_kv(t + 2, t & 1);
        if (t + 1 < 16) {
            if (t + 2 < 16) { asm volatile("cp.async.wait_group 1;"); }
            else            { asm volatile("cp.async.wait_group 0;"); }
            __syncthreads();
        }
    }

    // ---- epilogue: normalize + single fp16 into [M,1024] ----
    const float inv0 = 1.0f / l0, inv1 = 1.0f / l1;
    const int r0 = q0 + wid * 16 + (lane >> 2);
    const size_t m0i = (size_t)(b * 2048) + r0;
    const int colb = h * 64 + (lane & 3) * 2;
#pragma unroll
    for (int nd = 0; nd < 8; nd++) {
        *reinterpret_cast<uint32_t*>(&g_a[m0i * 1024 + colb + nd * 8]) =
            packh(o[nd][0] * inv0, o[nd][1] * inv0);
        *reinterpret_cast<uint32_t*>(&g_a[(m0i + 8) * 1024 + colb + nd * 8]) =
            packh(o[nd][2] * inv1, o[nd][3] * inv1);
    }
}

// ---------------------------------------------------------------------------
// Launch
// ---------------------------------------------------------------------------
extern "C" void kernel_launch(void* const* d_in, const int* in_sizes, int n_in,
                              void* d_out, int out_size)
{
    const float* x      = (const float*)d_in[0];
    const float* qkv_w  = (const float*)d_in[1];
    const float* qkv_b  = (const float*)d_in[2];
    const float* qn_w   = (const float*)d_in[3];
    const float* kn_w   = (const float*)d_in[4];
    const float* proj_w = (const float*)d_in[5];
    const float* proj_b = (const float*)d_in[6];
    float* out = (float*)d_out;

    cudaFuncSetAttribute(gemm_qkv_fused, cudaFuncAttributeMaxDynamicSharedMemorySize, GEMM_SMEM);
    cudaFuncSetAttribute(gemm_mma, cudaFuncAttributeMaxDynamicSharedMemorySize, GEMM_SMEM);
    cudaFuncSetAttribute(attn_mma, cudaFuncAttributeMaxDynamicSharedMemorySize, ATTN_SMEM);

    void *p_xh, *p_w1h, *p_w2h, *p_a;
    cudaGetSymbolAddress(&p_xh, g_xh);
    cudaGetSymbolAddress(&p_w1h, g_w1h);
    cudaGetSymbolAddress(&p_w2h, g_w2h);
    cudaGetSymbolAddress(&p_a, g_a);

    rope_table<<<128, 256>>>();

    cvt_all<<<(NX4 + NW14 + NW24 + 255) / 256, 256>>>(
        (const float4*)x, (const float4*)qkv_w, (const float4*)proj_w,
        (uint2*)p_xh, (uint2*)p_w1h, (uint2*)p_w2h);

    // 1. QKV projection + fused RMSNorm/RoPE/fp16 emit (head-major q/k/v)
    gemm_qkv_fused<<<dim3(K3_ / 128, M_ / 128), 256, GEMM_SMEM>>>(
        (const __half*)p_xh, (const __half*)p_w1h, qkv_b, qn_w, kn_w);

    // 2. Tensor-core flash attention (128 q/CTA, occ 2) -> g_a
    attn_mma<<<dim3(N_ / 128, H_, B_), 256, ATTN_SMEM>>>();

    // 3. Output projection -> d_out
    gemm_mma<<<dim3(C_ / 128, M_ / 128), 256, GEMM_SMEM>>>(
        (const __half*)p_a, (const __half*)p_w2h, proj_b, out, C_);
}